// round 13
// baseline (speedup 1.0000x reference)
#include <cuda_runtime.h>
#include <math.h>

#define T    2048
#define NF   6142     // 3T-2
#define M0C  4094     // 2T-2
#define BATCH 64

// ---------------- device scratch ----------------
__device__ float2 g_tw[512];         // e^{-2pi i k/4096}, k<512
__device__ float2 g_psi[2048];
__device__ float2 g_W[4096];         // FFT(chirp) in (64S + 8lam + r) slot order
__device__ float2 g_UH[4 * 2048];    // Htilde*phaseU, packed: slot = 32S + 4lam + r
__device__ float  g_A[9 * BATCH * T];
__device__ float  g_B[9 * BATCH * T];

__device__ __forceinline__ float2 cmul(float2 a, float2 b) {
    return make_float2(fmaf(a.x, b.x, -a.y * b.y), fmaf(a.x, b.y, a.y * b.x));
}
__device__ __forceinline__ float2 cmulc(float2 a, float2 b) {  // a * conj(b)
    return make_float2(fmaf(a.x, b.x, a.y * b.y), fmaf(a.y, b.x, -a.x * b.y));
}
__device__ __forceinline__ float2 cadd(float2 a, float2 b) { return make_float2(a.x + b.x, a.y + b.y); }
__device__ __forceinline__ float2 csub(float2 a, float2 b) { return make_float2(a.x - b.x, a.y - b.y); }
__device__ __forceinline__ int PAD(int e) { return e + (e >> 3) + (e >> 6); }
__device__ __forceinline__ int P16(int e) { return e + (e >> 4); }

#define RC8 0.70710678118654752440f

__device__ __forceinline__ void fwd8(float2* a) {
    float2 F0=cadd(a[0],a[4]), F1=csub(a[0],a[4]);
    float2 G0=cadd(a[2],a[6]), G1=csub(a[2],a[6]);
    float2 H0=cadd(a[1],a[5]), H1=csub(a[1],a[5]);
    float2 K0=cadd(a[3],a[7]), K1=csub(a[3],a[7]);
    float2 E0=cadd(F0,G0), E2=csub(F0,G0);
    float2 E1=make_float2(F1.x+G1.y, F1.y-G1.x);
    float2 E3=make_float2(F1.x-G1.y, F1.y+G1.x);
    float2 O0=cadd(H0,K0), O2=csub(H0,K0);
    float2 O1=make_float2(H1.x+K1.y, H1.y-K1.x);
    float2 O3=make_float2(H1.x-K1.y, H1.y+K1.x);
    float2 t1=make_float2(RC8*(O1.x+O1.y),  RC8*(O1.y-O1.x));
    float2 t2=make_float2(O2.y, -O2.x);
    float2 t3=make_float2(RC8*(O3.y-O3.x), -RC8*(O3.x+O3.y));
    a[0]=cadd(E0,O0); a[4]=csub(E0,O0);
    a[1]=cadd(E1,t1); a[5]=csub(E1,t1);
    a[2]=cadd(E2,t2); a[6]=csub(E2,t2);
    a[3]=cadd(E3,t3); a[7]=csub(E3,t3);
}

__device__ __forceinline__ void inv8(float2* a) {
    float2 F0=cadd(a[0],a[4]), F1=csub(a[0],a[4]);
    float2 G0=cadd(a[2],a[6]), G1=csub(a[2],a[6]);
    float2 H0=cadd(a[1],a[5]), H1=csub(a[1],a[5]);
    float2 K0=cadd(a[3],a[7]), K1=csub(a[3],a[7]);
    float2 E0=cadd(F0,G0), E2=csub(F0,G0);
    float2 E1=make_float2(F1.x-G1.y, F1.y+G1.x);
    float2 E3=make_float2(F1.x+G1.y, F1.y-G1.x);
    float2 O0=cadd(H0,K0), O2=csub(H0,K0);
    float2 O1=make_float2(H1.x-K1.y, H1.y+K1.x);
    float2 O3=make_float2(H1.x+K1.y, H1.y-K1.x);
    float2 t1=make_float2(RC8*(O1.x-O1.y),  RC8*(O1.x+O1.y));
    float2 t2=make_float2(-O2.y, O2.x);
    float2 t3=make_float2(-RC8*(O3.x+O3.y), RC8*(O3.x-O3.y));
    a[0]=cadd(E0,O0); a[4]=csub(E0,O0);
    a[1]=cadd(E1,t1); a[5]=csub(E1,t1);
    a[2]=cadd(E2,t2); a[6]=csub(E2,t2);
    a[3]=cadd(E3,t3); a[7]=csub(E3,t3);
}

// inverse 8-point DFT, only outputs 0..3
__device__ __forceinline__ void inv8_lo(float2* a) {
    float2 F0=cadd(a[0],a[4]), F1=csub(a[0],a[4]);
    float2 G0=cadd(a[2],a[6]), G1=csub(a[2],a[6]);
    float2 H0=cadd(a[1],a[5]), H1=csub(a[1],a[5]);
    float2 K0=cadd(a[3],a[7]), K1=csub(a[3],a[7]);
    float2 E0=cadd(F0,G0), E2=csub(F0,G0);
    float2 E1=make_float2(F1.x-G1.y, F1.y+G1.x);
    float2 E3=make_float2(F1.x+G1.y, F1.y-G1.x);
    float2 O0=cadd(H0,K0), O2=csub(H0,K0);
    float2 O1=make_float2(H1.x-K1.y, H1.y+K1.x);
    float2 O3=make_float2(H1.x+K1.y, H1.y-K1.x);
    float2 t1=make_float2(RC8*(O1.x-O1.y),  RC8*(O1.x+O1.y));
    float2 t2=make_float2(-O2.y, O2.x);
    float2 t3=make_float2(-RC8*(O3.x+O3.y), RC8*(O3.x-O3.y));
    a[0]=cadd(E0,O0); a[1]=cadd(E1,t1); a[2]=cadd(E2,t2); a[3]=cadd(E3,t3);
}

__device__ __forceinline__ void fwd8h(float2* a) {  // a[4..7] implied zero
    float2 a0=a[0], a1=a[1], a2=a[2], a3=a[3];
    float2 E0=cadd(a0,a2), E2=csub(a0,a2);
    float2 E1=make_float2(a0.x+a2.y, a0.y-a2.x);
    float2 E3=make_float2(a0.x-a2.y, a0.y+a2.x);
    float2 O0=cadd(a1,a3), O2=csub(a1,a3);
    float2 O1=make_float2(a1.x+a3.y, a1.y-a3.x);
    float2 O3=make_float2(a1.x-a3.y, a1.y+a3.x);
    float2 t1=make_float2(RC8*(O1.x+O1.y),  RC8*(O1.y-O1.x));
    float2 t2=make_float2(O2.y, -O2.x);
    float2 t3=make_float2(RC8*(O3.y-O3.x), -RC8*(O3.x+O3.y));
    a[0]=cadd(E0,O0); a[4]=csub(E0,O0);
    a[1]=cadd(E1,t1); a[5]=csub(E1,t1);
    a[2]=cadd(E2,t2); a[6]=csub(E2,t2);
    a[3]=cadd(E3,t3); a[7]=csub(E3,t3);
}

__device__ __forceinline__ void twid_fwd(float2* y, float2 w1) {
    float2 w2=cmul(w1,w1), w3=cmul(w2,w1), w4=cmul(w2,w2);
    float2 w5=cmul(w3,w2), w6=cmul(w3,w3), w7=cmul(w4,w3);
    y[1]=cmul(y[1],w1); y[2]=cmul(y[2],w2); y[3]=cmul(y[3],w3); y[4]=cmul(y[4],w4);
    y[5]=cmul(y[5],w5); y[6]=cmul(y[6],w6); y[7]=cmul(y[7],w7);
}
__device__ __forceinline__ void twid_inv(float2* y, float2 w1) {
    float2 w2=cmul(w1,w1), w3=cmul(w2,w1), w4=cmul(w2,w2);
    float2 w5=cmul(w3,w2), w6=cmul(w3,w3), w7=cmul(w4,w3);
    y[1]=cmulc(y[1],w1); y[2]=cmulc(y[2],w2); y[3]=cmulc(y[3],w3); y[4]=cmulc(y[4],w4);
    y[5]=cmulc(y[5],w5); y[6]=cmulc(y[6],w6); y[7]=cmulc(y[7],w7);
}

// fused: a[r] *= w0 * w1^r  /  conj(...)
__device__ __forceinline__ void twid_fwd_off(float2* a, float2 w0, float2 w1) {
    float2 c = w0;
    a[0] = cmul(a[0], c);
#pragma unroll
    for (int r = 1; r < 8; r++) { c = cmul(c, w1); a[r] = cmul(a[r], c); }
}
__device__ __forceinline__ void twid_inv_off(float2* a, float2 w0, float2 w1) {
    float2 c = w0;
    a[0] = cmulc(a[0], c);
#pragma unroll
    for (int r = 1; r < 8; r++) { c = cmul(c, w1); a[r] = cmulc(a[r], c); }
}

// 8x8 transpose via shfl_xor butterflies (lane bits 0..2)
__device__ __forceinline__ void transpose8(float2* a, int lane) {
#pragma unroll
    for (int b = 1; b < 8; b <<= 1) {
        bool hi = (lane & b) != 0;
#pragma unroll
        for (int jl = 0; jl < 8; jl++) {
            if (jl & b) continue;
            int jh = jl | b;
            float2 send = hi ? a[jl] : a[jh];
            float2 recv;
            recv.x = __shfl_xor_sync(0xffffffffu, send.x, b);
            recv.y = __shfl_xor_sync(0xffffffffu, send.y, b);
            if (hi) a[jl] = recv; else a[jh] = recv;
        }
    }
}

// warp-local 64-pt DFT, twiddle value passed directly
__device__ __forceinline__ void fwd64v(float2* a, int lane, float2 w64l) {
    fwd8(a); twid_fwd(a, w64l); transpose8(a, lane); fwd8(a);
}
__device__ __forceinline__ void inv64v(float2* a, int lane, float2 w64l) {
    inv8(a); transpose8(a, lane); twid_inv(a, w64l); inv8(a);
}
__device__ __forceinline__ void inv64v_lo(float2* a, int lane, float2 w64l) {
    inv8(a); transpose8(a, lane); twid_inv(a, w64l); inv8_lo(a);
}
// table variant (k_pre W role)
__device__ __forceinline__ void fwd64(float2* a, int lam, const float2* s_t64) {
    fwd8(a); twid_fwd(a, s_t64[lam]); transpose8(a, lam); fwd8(a);
}

// ---------------- 3x3 helpers ----------------
__device__ __forceinline__ void rod(float vx, float vy, float vz, float* M) {
    float t2 = vx * vx + vy * vy + vz * vz;
    float th = sqrtf(t2);
    float a, bb;
    if (t2 < 1e-8f) { a = 1.0f - t2 * (1.0f / 6.0f); bb = 0.5f - t2 * (1.0f / 24.0f); }
    else { a = sinf(th) / th; float sh = sinf(0.5f * th); bb = 2.0f * sh * sh / t2; }
    float ct = 1.0f - bb * t2;
    M[0] = ct + bb * vx * vx; M[1] = bb * vx * vy - a * vz; M[2] = bb * vx * vz + a * vy;
    M[3] = bb * vy * vx + a * vz; M[4] = ct + bb * vy * vy; M[5] = bb * vy * vz - a * vx;
    M[6] = bb * vz * vx - a * vy; M[7] = bb * vz * vy + a * vx; M[8] = ct + bb * vz * vz;
}
__device__ __forceinline__ void mm3(const float* A, const float* B, float* C) {
    float t[9];
#pragma unroll
    for (int i = 0; i < 3; i++)
#pragma unroll
        for (int j = 0; j < 3; j++)
            t[3 * i + j] = A[3 * i] * B[j] + A[3 * i + 1] * B[3 + j] + A[3 * i + 2] * B[6 + j];
#pragma unroll
    for (int k = 0; k < 9; k++) C[k] = t[k];
}
__device__ __forceinline__ void inv3(const float* A, float* B) {
    float c00 = A[4] * A[8] - A[5] * A[7];
    float c01 = A[5] * A[6] - A[3] * A[8];
    float c02 = A[3] * A[7] - A[4] * A[6];
    float id = 1.0f / (A[0] * c00 + A[1] * c01 + A[2] * c02);
    B[0] = c00 * id; B[1] = (A[2] * A[7] - A[1] * A[8]) * id; B[2] = (A[1] * A[5] - A[2] * A[4]) * id;
    B[3] = c01 * id; B[4] = (A[0] * A[8] - A[2] * A[6]) * id; B[5] = (A[2] * A[3] - A[0] * A[5]) * id;
    B[6] = c02 * id; B[7] = (A[1] * A[6] - A[0] * A[7]) * id; B[8] = (A[0] * A[4] - A[1] * A[3]) * id;
}

struct FnnW { const float *w1, *b1, *w2, *b2; };

extern __shared__ float2 smem_c[];

// ================= fused precompute kernel (unchanged from R11) =================
__global__ __launch_bounds__(512) void k_pre(
    const float* __restrict__ xd, const float* __restrict__ A1, const float* __restrict__ A2,
    FnnW wf, FnnW wg, FnnW wfp, FnnW wgp)
{
    int blk = blockIdx.x, tid = threadIdx.x;

    if (blk < 64) {
        float* sP = (float*)smem_c;        // 512*9
        float* sv = sP + 4608;             // 6
        int b = blk;
        if (tid == 0) {
            sv[0] = A1[7] - A1[5]; sv[1] = A1[2] - A1[6]; sv[2] = A1[3] - A1[1];
            sv[3] = A2[7] - A2[5]; sv[4] = A2[2] - A2[6]; sv[5] = A2[3] - A2[1];
        }
        __syncthreads();
        float v1x = sv[0], v1y = sv[1], v1z = sv[2], v2x = sv[3], v2y = sv[4], v2z = sv[5];
        float mine[9];
        int t0 = tid * 4;
        {
            float P[9] = {1, 0, 0, 0, 1, 0, 0, 0, 1};
            for (int tt = 0; tt < 4; tt++) {
                int t = t0 + tt;
                if (t == 0) continue;
                float z1 = xd[(b * T + t) * 2], z2 = xd[(b * T + t) * 2 + 1];
                float M[9];
                rod(z1 * v1x + z2 * v2x, z1 * v1y + z2 * v2y, z1 * v1z + z2 * v2z, M);
                mm3(P, M, P);
            }
#pragma unroll
            for (int k = 0; k < 9; k++) { mine[k] = P[k]; sP[tid * 9 + k] = P[k]; }
        }
        __syncthreads();
        for (int off = 1; off < 512; off <<= 1) {
            float Lm[9];
            bool a2 = tid >= off;
            if (a2)
#pragma unroll
                for (int k = 0; k < 9; k++) Lm[k] = sP[(tid - off) * 9 + k];
            __syncthreads();
            if (a2) {
                mm3(Lm, mine, mine);
#pragma unroll
                for (int k = 0; k < 9; k++) sP[tid * 9 + k] = mine[k];
            }
            __syncthreads();
        }
        {
            float X[9] = {1, 0, 0, 0, 1, 0, 0, 0, 1};
            if (tid > 0)
#pragma unroll
                for (int k = 0; k < 9; k++) X[k] = sP[(tid - 1) * 9 + k];
            for (int tt = 0; tt < 4; tt++) {
                int t = t0 + tt;
                if (t != 0) {
                    float z1 = xd[(b * T + t) * 2], z2 = xd[(b * T + t) * 2 + 1];
                    float M[9];
                    rod(z1 * v1x + z2 * v2x, z1 * v1y + z2 * v2y, z1 * v1z + z2 * v2z, M);
                    mm3(X, M, X);
                }
                float Bi[9];
                inv3(X, Bi);
#pragma unroll
                for (int c = 0; c < 9; c++) {
                    g_A[(c * BATCH + b) * T + t] = X[c];
                    g_B[(c * BATCH + b) * T + t] = Bi[c];
                }
            }
        }
    } else if (blk < 68) {
        int i = (blk - 64) * 512 + tid;
        float s, c;
        if (i < 512) {
            sincospif((float)i / 2048.0f, &s, &c);
            g_tw[i] = make_float2(c, -s);
        }
        long long j = i;
        long long e2 = (2LL * (T - 1) * (M0C + j) + j * j) % NF;
        sincospif(2.0f * (float)e2 / (float)NF, &s, &c);
        g_psi[i] = make_float2(c, s);
    } else if (blk == 68) {
        float2* s_tw  = smem_c;              // 512
        float2* s_buf = smem_c + 512;        // 4670
        float2* s_t64 = smem_c + 512 + 4670; // 8
        int t = tid;
        {
            float s, c;
            sincospif((float)t / 2048.0f, &s, &c);
            s_tw[t] = make_float2(c, -s);
        }
        __syncthreads();
        if (t < 8) s_t64[t] = s_tw[64 * t];
        __syncthreads();
        int lam = t & 7, S = t >> 3;
        float2 a[8];
#pragma unroll
        for (int r = 0; r < 8; r++) {
            int n = 64 * (lam + 8 * r) + S;
            float2 v;
            if (n == 2048) v = make_float2(0.f, 0.f);
            else {
                long long k = (n < 2048) ? n : (4096 - n);
                long long idx = (k * k) % (2LL * NF);
                float s, c;
                sincospif((float)idx / (float)NF, &s, &c);
                v = make_float2(c, -s);
            }
            a[r] = v;
        }
        fwd64(a, lam, s_t64);
        twid_fwd_off(a, s_tw[S * lam], s_tw[8 * S]);
#pragma unroll
        for (int r = 0; r < 8; r++) s_buf[PAD(512 * r + 64 * lam + S)] = a[r];
        __syncthreads();
#pragma unroll
        for (int r = 0; r < 8; r++) a[r] = s_buf[PAD(64 * S + 8 * r + lam)];
        fwd64(a, lam, s_t64);
#pragma unroll
        for (int r = 0; r < 8; r++) g_W[64 * S + 8 * lam + r] = a[r];
    } else {
        // H role — g_UH packed: slot(e) = 32*(e&63) + 4*((e>>6)&7) + (e>>9)
        float* s_q = (float*)smem_c;
        int hb = blk - 69;
        int q = hb >> 5;
        int jbase = (hb & 31) << 6;
        FnnW W = (q == 0) ? wf : (q == 1) ? wg : (q == 2) ? wfp : wgp;
        for (int p = tid; p < 2048; p += 512) {
            float x = (q == 0 || q == 2) ? (float)(T - 1 - p) : (float)p;
            float z = W.b2[0];
#pragma unroll
            for (int h = 0; h < 5; h++)
                z += W.w2[h] * tanhf(W.w1[h] * x + W.b1[h]);
            s_q[p] = z * expf(-5.0f * x);
        }
        __syncthreads();
        int warp = tid >> 5, lane = tid & 31;
        float2 ph[4], st[4], acc[4];
#pragma unroll
        for (int u = 0; u < 4; u++) {
            int j = jbase + 4 * warp + u;
            long long base = j + (T - 1);
            long long idx0 = (base * (long long)(lane + T - 1)) % NF;
            float s, c;
            sincospif(2.0f * (float)idx0 / (float)NF, &s, &c);
            ph[u] = make_float2(c, -s);
            long long idxs = (base * 32LL) % NF;
            sincospif(2.0f * (float)idxs / (float)NF, &s, &c);
            st[u] = make_float2(c, -s);
            acc[u] = make_float2(0.f, 0.f);
        }
#pragma unroll 4
        for (int it = 0; it < 64; it++) {
            float v = s_q[lane + 32 * it];
#pragma unroll
            for (int u = 0; u < 4; u++) {
                acc[u].x = fmaf(v, ph[u].x, acc[u].x);
                acc[u].y = fmaf(v, ph[u].y, acc[u].y);
                ph[u] = cmul(ph[u], st[u]);
            }
        }
#pragma unroll
        for (int u = 0; u < 4; u++) {
            for (int off = 16; off; off >>= 1) {
                acc[u].x += __shfl_down_sync(0xffffffffu, acc[u].x, off);
                acc[u].y += __shfl_down_sync(0xffffffffu, acc[u].y, off);
            }
        }
        if (lane == 0) {
#pragma unroll
            for (int u = 0; u < 4; u++) {
                int j = jbase + 4 * warp + u;
                long long idxU = (2LL * j * M0C + (long long)j * j) % (2LL * NF);
                float s, c;
                sincospif((float)idxU / (float)NF, &s, &c);
                int slot = 32 * (j & 63) + 4 * ((j >> 6) & 7) + (j >> 9);
                g_UH[q * 2048 + slot] = cmul(acc[u], make_float2(c, s));
            }
        }
    }
}

// ================= main kernel: 2 pairs per block =================
// smem: tw 512 | Z 2*2177 | E1 4670 | E2 4670 = 14206 f2 = 113,648 B
#define SMEM_MAIN_F2 (512 + 2 * 2177 + 4670 + 4670)

__global__ __launch_bounds__(512, 2) void k_main(float* __restrict__ out) {
    float2* s_tw = smem_c;              // 512
    float2* s_Z  = smem_c + 512;        // 2*2177
    float2* sE1  = smem_c + 512 + 4354; // 4670
    float2* sE2  = sE1 + 4670;          // 4670

    int blk = blockIdx.x;
    int t = threadIdx.x;

    s_tw[t] = g_tw[t & 511];
    __syncthreads();

    // ===== phase 0: TWO packed 2048-pt FFTs, one per 256-thread half =====
    int half = t >> 8, tl = t & 255;
    {
        int idxp = 2 * blk + half;
        int bh = idxp / 9, ch = idxp % 9;
        const float* ArH = g_A + (ch * BATCH + bh) * T;
        const float* AiH = g_B + (ch * BATCH + bh) * T;
        float2* E1h = sE1 + half * 2335;
        float2* E2h = sE2 + half * 2335;
        float2* Zh  = s_Z + half * 2177;

        float2 a[8];
#pragma unroll
        for (int j = 0; j < 8; j++) {
            int i = tl + 256 * j;
            a[j] = make_float2(AiH[i], ArH[i]);   // z = Xir + i*Xr
        }
        fwd8(a); twid_fwd(a, s_tw[2 * tl]);
#pragma unroll
        for (int r = 0; r < 8; r++) E1h[PAD(256 * r + tl)] = a[r];
        __syncthreads();
        {   // stage2: S=256 q=32  E1->E2
            int pb = 256 * (tl >> 5), pk = tl & 31;
#pragma unroll
            for (int j = 0; j < 8; j++) a[j] = E1h[PAD(pb + pk + 32 * j)];
            fwd8(a); twid_fwd(a, s_tw[16 * pk]);
#pragma unroll
            for (int r = 0; r < 8; r++) E2h[PAD(pb + 32 * r + pk)] = a[r];
        }
        __syncthreads();
        {   // stage3: S=32 q=4  E2->E1
            int pb = 32 * (tl >> 2), pk = tl & 3;
#pragma unroll
            for (int j = 0; j < 8; j++) a[j] = E2h[PAD(pb + pk + 4 * j)];
            fwd8(a); twid_fwd(a, s_tw[128 * pk]);
#pragma unroll
            for (int r = 0; r < 8; r++) E1h[PAD(pb + 4 * r + pk)] = a[r];
        }
        __syncthreads();
        // stage4: radix-4 x2, unscramble  E1->Z (P16 pad)
#pragma unroll
        for (int h = 0; h < 2; h++) {
            int B = 2 * tl + h;
            float2 b4[4];
#pragma unroll
            for (int j = 0; j < 4; j++) b4[j] = E1h[PAD(4 * B + j)];
            float2 e0 = cadd(b4[0], b4[2]), e1 = csub(b4[0], b4[2]);
            float2 o0 = cadd(b4[1], b4[3]), o1 = csub(b4[1], b4[3]);
            float2 y0 = cadd(e0, o0), y2 = csub(e0, o0);
            float2 y1 = make_float2(e1.x + o1.y, e1.y - o1.x);
            float2 y3 = make_float2(e1.x - o1.y, e1.y + o1.x);
            int f = (B >> 6) + 8 * ((B >> 3) & 7) + 64 * (B & 7);
            int fz = P16(f);
            Zh[fz] = y0; Zh[fz + 544] = y1; Zh[fz + 1088] = y2; Zh[fz + 1632] = y3;
            if (B == 0) Zh[2176] = y0;   // dup Z[0] at P16(2048)
        }
    }
    __syncthreads();

    // ===== per-thread round constants =====
    const float sc = 1.0f / (4096.0f * (float)NF);
    const int lam = t & 7;
    const int S   = t >> 3;
    const float2 w64l = s_tw[64 * lam];
    const float2 wS0  = s_tw[S * lam];
    const float2 wS1  = s_tw[8 * S];
    const int B1  = PAD(64 * lam + S);
    const int B2  = 73 * S + lam;
    const int B1z = P16(64 * lam + S);
    const int BMz = P16(512 - 64 * lam - S);
    const float2* Wp = g_W + 64 * S + 8 * lam;
    const int BT = PAD(t);

    // ===== chirp rounds, pair-sequential =====
    for (int pair = 0; pair < 2; pair++) {
        int idxp = 2 * blk + pair;
        int b = idxp / 9, c = idxp % 9;
        const float2* Zp = s_Z + pair * 2177;
        float2 c1r[4], Pr[4];
        float2 a[8];

#pragma unroll
        for (int s = 0; s < 4; s++) {
            bool useIr = (s == 0 || s == 2);
            const float4* UHp = (const float4*)(g_UH + s * 2048 + 4 * t);
            float4 uh01 = UHp[0], uh23 = UHp[1];

            // step1
#pragma unroll
            for (int r = 0; r < 4; r++) {
                float2 Zj = Zp[B1z + 544 * r];
                float2 Zm = Zp[BMz + 544 * (3 - r)];
                float2 X = useIr
                    ? make_float2(0.5f * (Zj.x + Zm.x), 0.5f * (Zj.y - Zm.y))
                    : make_float2(0.5f * (Zj.y + Zm.y), 0.5f * (Zm.x - Zj.x));
                float2 uh = (r == 0) ? make_float2(uh01.x, uh01.y)
                          : (r == 1) ? make_float2(uh01.z, uh01.w)
                          : (r == 2) ? make_float2(uh23.x, uh23.y)
                                     : make_float2(uh23.z, uh23.w);
                a[r] = cmul(X, uh);
            }
            fwd8h(a); twid_fwd(a, w64l); transpose8(a, t); fwd8(a);
            twid_fwd_off(a, wS0, wS1);
#pragma unroll
            for (int r = 0; r < 8; r++) sE1[B1 + 584 * r] = a[r];
            __syncthreads();

            // middle
#pragma unroll
            for (int r = 0; r < 8; r++) a[r] = sE1[B2 + 9 * r];
            fwd64v(a, t, w64l);
            {
                const float4* W4 = (const float4*)Wp;
                float4 w = W4[0];
                a[0] = cmul(a[0], make_float2(w.x, w.y)); a[1] = cmul(a[1], make_float2(w.z, w.w));
                w = W4[1];
                a[2] = cmul(a[2], make_float2(w.x, w.y)); a[3] = cmul(a[3], make_float2(w.z, w.w));
                w = W4[2];
                a[4] = cmul(a[4], make_float2(w.x, w.y)); a[5] = cmul(a[5], make_float2(w.z, w.w));
                w = W4[3];
                a[6] = cmul(a[6], make_float2(w.x, w.y)); a[7] = cmul(a[7], make_float2(w.z, w.w));
            }
            inv64v(a, t, w64l);
            twid_inv_off(a, wS0, wS1);
#pragma unroll
            for (int r = 0; r < 8; r++) sE2[B1 + 584 * r] = a[r];
            __syncthreads();

            // step1'
#pragma unroll
            for (int r = 0; r < 8; r++) a[r] = sE2[B2 + 9 * r];
            inv64v_lo(a, t, w64l);
#pragma unroll
            for (int j = 0; j < 4; j++) {
                float2 v = make_float2(a[j].x * sc, a[j].y * sc);
                if (s == 0) c1r[j] = v;
                else if (s == 1) Pr[j] = cmul(c1r[j], v);
                else if (s == 2) c1r[j] = v;
                else {
                    float2 p = cmul(c1r[j], v);
                    Pr[j].x += p.x; Pr[j].y += p.y;
                }
            }
        }

        // output for this pair: permute to m = t + 512j layout
#pragma unroll
        for (int j = 0; j < 4; j++) sE1[B1 + 584 * j] = Pr[j];
        __syncthreads();
#pragma unroll
        for (int j = 0; j < 4; j++) {
            float2 p = sE1[BT + 584 * j];
            int m = t + 512 * j;
            float2 psi = g_psi[m];
            out[(b * T + m) * 9 + c] = p.x * psi.x - p.y * psi.y;
        }
        __syncthreads();   // protect sE1 before next pair's stage1 writes
    }
}

// ---------------- launch ----------------
extern "C" void kernel_launch(void* const* d_in, const int* in_sizes, int n_in,
                              void* d_out, int out_size) {
    const float* xd = (const float*)d_in[0];
    const float* A1 = (const float*)d_in[1];
    const float* A2 = (const float*)d_in[2];
    FnnW wf  = {(const float*)d_in[3],  (const float*)d_in[4],  (const float*)d_in[5],  (const float*)d_in[6]};
    FnnW wg  = {(const float*)d_in[7],  (const float*)d_in[8],  (const float*)d_in[9],  (const float*)d_in[10]};
    FnnW wfp = {(const float*)d_in[11], (const float*)d_in[12], (const float*)d_in[13], (const float*)d_in[14]};
    FnnW wgp = {(const float*)d_in[15], (const float*)d_in[16], (const float*)d_in[17], (const float*)d_in[18]};
    float* out = (float*)d_out;

    int smem_pre  = (512 + 4670 + 8 + 64) * sizeof(float2);
    int smem_main = SMEM_MAIN_F2 * sizeof(float2);             // 113,648 B
    cudaFuncSetAttribute(k_pre,  cudaFuncAttributeMaxDynamicSharedMemorySize, smem_pre);
    cudaFuncSetAttribute(k_main, cudaFuncAttributeMaxDynamicSharedMemorySize, smem_main);

    k_pre<<<197, 512, smem_pre>>>(xd, A1, A2, wf, wg, wfp, wgp);
    k_main<<<BATCH * 9 / 2, 512, smem_main>>>(out);
}

// round 14
// speedup vs baseline: 1.0385x; 1.0385x over previous
#include <cuda_runtime.h>
#include <math.h>

#define T    2048
#define NF   6142     // 3T-2
#define M0C  4094     // 2T-2
#define BATCH 64
#define NPRE 197
#define NMAIN 576

// ---------------- device scratch ----------------
__device__ float2 g_tw[512];
__device__ float2 g_psi[2048];
__device__ float2 g_W[4096];         // FFT(chirp), slot (64S + 8lam + r)
__device__ float2 g_UH[4 * 2048];    // Htilde*phaseU, packed slot = 32S + 4lam + r
__device__ float  g_A[9 * BATCH * T];
__device__ float  g_B[9 * BATCH * T];
__device__ unsigned g_done = 0;      // producer completion counter
__device__ unsigned g_pass = 0;      // consumer gate-passed counter

__device__ __forceinline__ float2 cmul(float2 a, float2 b) {
    return make_float2(fmaf(a.x, b.x, -a.y * b.y), fmaf(a.x, b.y, a.y * b.x));
}
__device__ __forceinline__ float2 cmulc(float2 a, float2 b) {
    return make_float2(fmaf(a.x, b.x, a.y * b.y), fmaf(a.y, b.x, -a.x * b.y));
}
__device__ __forceinline__ float2 cadd(float2 a, float2 b) { return make_float2(a.x + b.x, a.y + b.y); }
__device__ __forceinline__ float2 csub(float2 a, float2 b) { return make_float2(a.x - b.x, a.y - b.y); }
__device__ __forceinline__ int PAD(int e) { return e + (e >> 3) + (e >> 6); }

#define RC8 0.70710678118654752440f

__device__ __forceinline__ void fwd8(float2* a) {
    float2 F0=cadd(a[0],a[4]), F1=csub(a[0],a[4]);
    float2 G0=cadd(a[2],a[6]), G1=csub(a[2],a[6]);
    float2 H0=cadd(a[1],a[5]), H1=csub(a[1],a[5]);
    float2 K0=cadd(a[3],a[7]), K1=csub(a[3],a[7]);
    float2 E0=cadd(F0,G0), E2=csub(F0,G0);
    float2 E1=make_float2(F1.x+G1.y, F1.y-G1.x);
    float2 E3=make_float2(F1.x-G1.y, F1.y+G1.x);
    float2 O0=cadd(H0,K0), O2=csub(H0,K0);
    float2 O1=make_float2(H1.x+K1.y, H1.y-K1.x);
    float2 O3=make_float2(H1.x-K1.y, H1.y+K1.x);
    float2 t1=make_float2(RC8*(O1.x+O1.y),  RC8*(O1.y-O1.x));
    float2 t2=make_float2(O2.y, -O2.x);
    float2 t3=make_float2(RC8*(O3.y-O3.x), -RC8*(O3.x+O3.y));
    a[0]=cadd(E0,O0); a[4]=csub(E0,O0);
    a[1]=cadd(E1,t1); a[5]=csub(E1,t1);
    a[2]=cadd(E2,t2); a[6]=csub(E2,t2);
    a[3]=cadd(E3,t3); a[7]=csub(E3,t3);
}

__device__ __forceinline__ void inv8(float2* a) {
    float2 F0=cadd(a[0],a[4]), F1=csub(a[0],a[4]);
    float2 G0=cadd(a[2],a[6]), G1=csub(a[2],a[6]);
    float2 H0=cadd(a[1],a[5]), H1=csub(a[1],a[5]);
    float2 K0=cadd(a[3],a[7]), K1=csub(a[3],a[7]);
    float2 E0=cadd(F0,G0), E2=csub(F0,G0);
    float2 E1=make_float2(F1.x-G1.y, F1.y+G1.x);
    float2 E3=make_float2(F1.x+G1.y, F1.y-G1.x);
    float2 O0=cadd(H0,K0), O2=csub(H0,K0);
    float2 O1=make_float2(H1.x-K1.y, H1.y+K1.x);
    float2 O3=make_float2(H1.x+K1.y, H1.y-K1.x);
    float2 t1=make_float2(RC8*(O1.x-O1.y),  RC8*(O1.x+O1.y));
    float2 t2=make_float2(-O2.y, O2.x);
    float2 t3=make_float2(-RC8*(O3.x+O3.y), RC8*(O3.x-O3.y));
    a[0]=cadd(E0,O0); a[4]=csub(E0,O0);
    a[1]=cadd(E1,t1); a[5]=csub(E1,t1);
    a[2]=cadd(E2,t2); a[6]=csub(E2,t2);
    a[3]=cadd(E3,t3); a[7]=csub(E3,t3);
}

__device__ __forceinline__ void inv8_lo(float2* a) {
    float2 F0=cadd(a[0],a[4]), F1=csub(a[0],a[4]);
    float2 G0=cadd(a[2],a[6]), G1=csub(a[2],a[6]);
    float2 H0=cadd(a[1],a[5]), H1=csub(a[1],a[5]);
    float2 K0=cadd(a[3],a[7]), K1=csub(a[3],a[7]);
    float2 E0=cadd(F0,G0), E2=csub(F0,G0);
    float2 E1=make_float2(F1.x-G1.y, F1.y+G1.x);
    float2 E3=make_float2(F1.x+G1.y, F1.y-G1.x);
    float2 O0=cadd(H0,K0), O2=csub(H0,K0);
    float2 O1=make_float2(H1.x-K1.y, H1.y+K1.x);
    float2 O3=make_float2(H1.x+K1.y, H1.y-K1.x);
    float2 t1=make_float2(RC8*(O1.x-O1.y),  RC8*(O1.x+O1.y));
    float2 t2=make_float2(-O2.y, O2.x);
    float2 t3=make_float2(-RC8*(O3.x+O3.y), RC8*(O3.x-O3.y));
    a[0]=cadd(E0,O0); a[1]=cadd(E1,t1); a[2]=cadd(E2,t2); a[3]=cadd(E3,t3);
}

__device__ __forceinline__ void fwd8h(float2* a) {
    float2 a0=a[0], a1=a[1], a2=a[2], a3=a[3];
    float2 E0=cadd(a0,a2), E2=csub(a0,a2);
    float2 E1=make_float2(a0.x+a2.y, a0.y-a2.x);
    float2 E3=make_float2(a0.x-a2.y, a0.y+a2.x);
    float2 O0=cadd(a1,a3), O2=csub(a1,a3);
    float2 O1=make_float2(a1.x+a3.y, a1.y-a3.x);
    float2 O3=make_float2(a1.x-a3.y, a1.y+a3.x);
    float2 t1=make_float2(RC8*(O1.x+O1.y),  RC8*(O1.y-O1.x));
    float2 t2=make_float2(O2.y, -O2.x);
    float2 t3=make_float2(RC8*(O3.y-O3.x), -RC8*(O3.x+O3.y));
    a[0]=cadd(E0,O0); a[4]=csub(E0,O0);
    a[1]=cadd(E1,t1); a[5]=csub(E1,t1);
    a[2]=cadd(E2,t2); a[6]=csub(E2,t2);
    a[3]=cadd(E3,t3); a[7]=csub(E3,t3);
}

__device__ __forceinline__ void twid_fwd(float2* y, float2 w1) {
    float2 w2=cmul(w1,w1), w3=cmul(w2,w1), w4=cmul(w2,w2);
    float2 w5=cmul(w3,w2), w6=cmul(w3,w3), w7=cmul(w4,w3);
    y[1]=cmul(y[1],w1); y[2]=cmul(y[2],w2); y[3]=cmul(y[3],w3); y[4]=cmul(y[4],w4);
    y[5]=cmul(y[5],w5); y[6]=cmul(y[6],w6); y[7]=cmul(y[7],w7);
}
__device__ __forceinline__ void twid_inv(float2* y, float2 w1) {
    float2 w2=cmul(w1,w1), w3=cmul(w2,w1), w4=cmul(w2,w2);
    float2 w5=cmul(w3,w2), w6=cmul(w3,w3), w7=cmul(w4,w3);
    y[1]=cmulc(y[1],w1); y[2]=cmulc(y[2],w2); y[3]=cmulc(y[3],w3); y[4]=cmulc(y[4],w4);
    y[5]=cmulc(y[5],w5); y[6]=cmulc(y[6],w6); y[7]=cmulc(y[7],w7);
}
__device__ __forceinline__ void twid_fwd_off(float2* a, float2 w0, float2 w1) {
    float2 c = w0;
    a[0] = cmul(a[0], c);
#pragma unroll
    for (int r = 1; r < 8; r++) { c = cmul(c, w1); a[r] = cmul(a[r], c); }
}
__device__ __forceinline__ void twid_inv_off(float2* a, float2 w0, float2 w1) {
    float2 c = w0;
    a[0] = cmulc(a[0], c);
#pragma unroll
    for (int r = 1; r < 8; r++) { c = cmul(c, w1); a[r] = cmulc(a[r], c); }
}

__device__ __forceinline__ void transpose8(float2* a, int lane) {
#pragma unroll
    for (int b = 1; b < 8; b <<= 1) {
        bool hi = (lane & b) != 0;
#pragma unroll
        for (int jl = 0; jl < 8; jl++) {
            if (jl & b) continue;
            int jh = jl | b;
            float2 send = hi ? a[jl] : a[jh];
            float2 recv;
            recv.x = __shfl_xor_sync(0xffffffffu, send.x, b);
            recv.y = __shfl_xor_sync(0xffffffffu, send.y, b);
            if (hi) a[jl] = recv; else a[jh] = recv;
        }
    }
}

__device__ __forceinline__ void fwd64v(float2* a, int lane, float2 w64l) {
    fwd8(a); twid_fwd(a, w64l); transpose8(a, lane); fwd8(a);
}
__device__ __forceinline__ void inv64v(float2* a, int lane, float2 w64l) {
    inv8(a); transpose8(a, lane); twid_inv(a, w64l); inv8(a);
}
__device__ __forceinline__ void inv64v_lo(float2* a, int lane, float2 w64l) {
    inv8(a); transpose8(a, lane); twid_inv(a, w64l); inv8_lo(a);
}

// ---------------- 3x3 helpers ----------------
__device__ __forceinline__ void rod(float vx, float vy, float vz, float* M) {
    float t2 = vx * vx + vy * vy + vz * vz;
    float th = sqrtf(t2);
    float a, bb;
    if (t2 < 1e-8f) { a = 1.0f - t2 * (1.0f / 6.0f); bb = 0.5f - t2 * (1.0f / 24.0f); }
    else { a = sinf(th) / th; float sh = sinf(0.5f * th); bb = 2.0f * sh * sh / t2; }
    float ct = 1.0f - bb * t2;
    M[0] = ct + bb * vx * vx; M[1] = bb * vx * vy - a * vz; M[2] = bb * vx * vz + a * vy;
    M[3] = bb * vy * vx + a * vz; M[4] = ct + bb * vy * vy; M[5] = bb * vy * vz - a * vx;
    M[6] = bb * vz * vx - a * vy; M[7] = bb * vz * vy + a * vx; M[8] = ct + bb * vz * vz;
}
__device__ __forceinline__ void mm3(const float* A, const float* B, float* C) {
    float t[9];
#pragma unroll
    for (int i = 0; i < 3; i++)
#pragma unroll
        for (int j = 0; j < 3; j++)
            t[3 * i + j] = A[3 * i] * B[j] + A[3 * i + 1] * B[3 + j] + A[3 * i + 2] * B[6 + j];
#pragma unroll
    for (int k = 0; k < 9; k++) C[k] = t[k];
}
__device__ __forceinline__ void inv3(const float* A, float* B) {
    float c00 = A[4] * A[8] - A[5] * A[7];
    float c01 = A[5] * A[6] - A[3] * A[8];
    float c02 = A[3] * A[7] - A[4] * A[6];
    float id = 1.0f / (A[0] * c00 + A[1] * c01 + A[2] * c02);
    B[0] = c00 * id; B[1] = (A[2] * A[7] - A[1] * A[8]) * id; B[2] = (A[1] * A[5] - A[2] * A[4]) * id;
    B[3] = c01 * id; B[4] = (A[0] * A[8] - A[2] * A[6]) * id; B[5] = (A[2] * A[3] - A[0] * A[5]) * id;
    B[6] = c02 * id; B[7] = (A[1] * A[6] - A[0] * A[7]) * id; B[8] = (A[0] * A[4] - A[1] * A[3]) * id;
}

struct FnnW { const float *w1, *b1, *w2, *b2; };

extern __shared__ float2 smem_c[];

// smem: tw 512 | Z 2337 | E1 4670 | E2 4670 = 12189 f2 = 97,512 B
#define SMEM_ALL_F2 (512 + 2337 + 4670 + 4670)

// ================= fused single kernel =================
// blocks 0..63 scan | 64..67 tables | 68 W | 69..196 H | 197..772 main
__global__ __launch_bounds__(512, 2) void k_all(
    float* __restrict__ out,
    const float* __restrict__ xd, const float* __restrict__ A1, const float* __restrict__ A2,
    FnnW wf, FnnW wg, FnnW wfp, FnnW wgp)
{
    int blk = blockIdx.x, tid = threadIdx.x;

    if (blk < NPRE) {
        // =================== PRODUCER ROLES ===================
        if (blk < 64) {
            float* sP = (float*)smem_c;        // 512*9
            float* sv = sP + 4608;             // 6
            int b = blk;
            if (tid == 0) {
                sv[0] = A1[7] - A1[5]; sv[1] = A1[2] - A1[6]; sv[2] = A1[3] - A1[1];
                sv[3] = A2[7] - A2[5]; sv[4] = A2[2] - A2[6]; sv[5] = A2[3] - A2[1];
            }
            __syncthreads();
            float v1x = sv[0], v1y = sv[1], v1z = sv[2], v2x = sv[3], v2y = sv[4], v2z = sv[5];
            float mine[9];
            int t0 = tid * 4;
            {
                float P[9] = {1, 0, 0, 0, 1, 0, 0, 0, 1};
                for (int tt = 0; tt < 4; tt++) {
                    int t = t0 + tt;
                    if (t == 0) continue;
                    float z1 = xd[(b * T + t) * 2], z2 = xd[(b * T + t) * 2 + 1];
                    float M[9];
                    rod(z1 * v1x + z2 * v2x, z1 * v1y + z2 * v2y, z1 * v1z + z2 * v2z, M);
                    mm3(P, M, P);
                }
#pragma unroll
                for (int k = 0; k < 9; k++) { mine[k] = P[k]; sP[tid * 9 + k] = P[k]; }
            }
            __syncthreads();
            for (int off = 1; off < 512; off <<= 1) {
                float Lm[9];
                bool a2 = tid >= off;
                if (a2)
#pragma unroll
                    for (int k = 0; k < 9; k++) Lm[k] = sP[(tid - off) * 9 + k];
                __syncthreads();
                if (a2) {
                    mm3(Lm, mine, mine);
#pragma unroll
                    for (int k = 0; k < 9; k++) sP[tid * 9 + k] = mine[k];
                }
                __syncthreads();
            }
            {
                float X[9] = {1, 0, 0, 0, 1, 0, 0, 0, 1};
                if (tid > 0)
#pragma unroll
                    for (int k = 0; k < 9; k++) X[k] = sP[(tid - 1) * 9 + k];
                for (int tt = 0; tt < 4; tt++) {
                    int t = t0 + tt;
                    if (t != 0) {
                        float z1 = xd[(b * T + t) * 2], z2 = xd[(b * T + t) * 2 + 1];
                        float M[9];
                        rod(z1 * v1x + z2 * v2x, z1 * v1y + z2 * v2y, z1 * v1z + z2 * v2z, M);
                        mm3(X, M, X);
                    }
                    float Bi[9];
                    inv3(X, Bi);
#pragma unroll
                    for (int c = 0; c < 9; c++) {
                        g_A[(c * BATCH + b) * T + t] = X[c];
                        g_B[(c * BATCH + b) * T + t] = Bi[c];
                    }
                }
            }
        } else if (blk < 68) {
            int i = (blk - 64) * 512 + tid;
            float s, c;
            if (i < 512) {
                sincospif((float)i / 2048.0f, &s, &c);
                g_tw[i] = make_float2(c, -s);
            }
            long long j = i;
            long long e2 = (2LL * (T - 1) * (M0C + j) + j * j) % NF;
            sincospif(2.0f * (float)e2 / (float)NF, &s, &c);
            g_psi[i] = make_float2(c, s);
        } else if (blk == 68) {
            float2* s_tw  = smem_c;              // 512
            float2* s_buf = smem_c + 512;        // 4670
            int t = tid;
            {
                float s, c;
                sincospif((float)t / 2048.0f, &s, &c);
                s_tw[t] = make_float2(c, -s);
            }
            __syncthreads();
            int lam = t & 7, S = t >> 3;
            float2 w64l = s_tw[64 * lam];
            float2 a[8];
#pragma unroll
            for (int r = 0; r < 8; r++) {
                int n = 64 * (lam + 8 * r) + S;
                float2 v;
                if (n == 2048) v = make_float2(0.f, 0.f);
                else {
                    long long k = (n < 2048) ? n : (4096 - n);
                    long long idx = (k * k) % (2LL * NF);
                    float s, c;
                    sincospif((float)idx / (float)NF, &s, &c);
                    v = make_float2(c, -s);
                }
                a[r] = v;
            }
            fwd64v(a, t, w64l);
            twid_fwd_off(a, s_tw[S * lam], s_tw[8 * S]);
#pragma unroll
            for (int r = 0; r < 8; r++) s_buf[PAD(512 * r + 64 * lam + S)] = a[r];
            __syncthreads();
#pragma unroll
            for (int r = 0; r < 8; r++) a[r] = s_buf[PAD(64 * S + 8 * r + lam)];
            fwd64v(a, t, w64l);
#pragma unroll
            for (int r = 0; r < 8; r++) g_W[64 * S + 8 * lam + r] = a[r];
        } else {
            // H role — g_UH packed: slot(e) = 32*(e&63) + 4*((e>>6)&7) + (e>>9)
            float* s_q = (float*)smem_c;
            int hb = blk - 69;
            int q = hb >> 5;
            int jbase = (hb & 31) << 6;
            FnnW W = (q == 0) ? wf : (q == 1) ? wg : (q == 2) ? wfp : wgp;
            for (int p = tid; p < 2048; p += 512) {
                float x = (q == 0 || q == 2) ? (float)(T - 1 - p) : (float)p;
                float z = W.b2[0];
#pragma unroll
                for (int h = 0; h < 5; h++)
                    z += W.w2[h] * tanhf(W.w1[h] * x + W.b1[h]);
                s_q[p] = z * expf(-5.0f * x);
            }
            __syncthreads();
            int warp = tid >> 5, lane = tid & 31;
            float2 ph[4], st[4], acc[4];
#pragma unroll
            for (int u = 0; u < 4; u++) {
                int j = jbase + 4 * warp + u;
                long long base = j + (T - 1);
                long long idx0 = (base * (long long)(lane + T - 1)) % NF;
                float s, c;
                sincospif(2.0f * (float)idx0 / (float)NF, &s, &c);
                ph[u] = make_float2(c, -s);
                long long idxs = (base * 32LL) % NF;
                sincospif(2.0f * (float)idxs / (float)NF, &s, &c);
                st[u] = make_float2(c, -s);
                acc[u] = make_float2(0.f, 0.f);
            }
#pragma unroll 4
            for (int it = 0; it < 64; it++) {
                float v = s_q[lane + 32 * it];
#pragma unroll
                for (int u = 0; u < 4; u++) {
                    acc[u].x = fmaf(v, ph[u].x, acc[u].x);
                    acc[u].y = fmaf(v, ph[u].y, acc[u].y);
                    ph[u] = cmul(ph[u], st[u]);
                }
            }
#pragma unroll
            for (int u = 0; u < 4; u++) {
                for (int off = 16; off; off >>= 1) {
                    acc[u].x += __shfl_down_sync(0xffffffffu, acc[u].x, off);
                    acc[u].y += __shfl_down_sync(0xffffffffu, acc[u].y, off);
                }
            }
            if (lane == 0) {
#pragma unroll
                for (int u = 0; u < 4; u++) {
                    int j = jbase + 4 * warp + u;
                    long long idxU = (2LL * j * M0C + (long long)j * j) % (2LL * NF);
                    float s, c;
                    sincospif((float)idxU / (float)NF, &s, &c);
                    int slot = 32 * (j & 63) + 4 * ((j >> 6) & 7) + (j >> 9);
                    g_UH[q * 2048 + slot] = cmul(acc[u], make_float2(c, s));
                }
            }
        }
        // signal completion
        __threadfence();
        __syncthreads();
        if (tid == 0) atomicAdd(&g_done, 1u);
        return;
    }

    // =================== CONSUMER (main) ===================
    // gate: wait for all producers
    if (tid == 0) {
        while (atomicAdd(&g_done, 0u) < (unsigned)NPRE) __nanosleep(200);
        __threadfence();
        unsigned p = atomicAdd(&g_pass, 1u) + 1u;
        if (p == (unsigned)NMAIN) {   // last consumer through: reset for next launch
            g_done = 0u; g_pass = 0u;
            __threadfence();
        }
    }
    __syncthreads();

    float2* s_tw = smem_c;              // 512
    float2* s_Z  = smem_c + 512;        // 2337 (padded 2048 + dup slot 2336)
    float2* sE1  = smem_c + 2849;       // 4670
    float2* sE2  = sE1 + 4670;          // 4670

    int idxp = blk - NPRE;
    int b = idxp / 9, c = idxp % 9;
    int t = tid;

    s_tw[t] = g_tw[t & 511];
    __syncthreads();

    const float* Ar = g_A + (c * BATCH + b) * T;
    const float* Ai = g_B + (c * BATCH + b) * T;

    // ===== phase 0: packed 2048-pt FFT (256 active threads) =====
    float2 a[8];
    if (t < 256) {
#pragma unroll
        for (int j = 0; j < 8; j++) {
            int i = t + 256 * j;
            a[j] = make_float2(Ai[i], Ar[i]);   // z = Xir + i*Xr
        }
        fwd8(a); twid_fwd(a, s_tw[2 * t]);
#pragma unroll
        for (int r = 0; r < 8; r++) sE1[PAD(256 * r + t)] = a[r];
    }
    __syncthreads();
    if (t < 256) {  // stage2: S=256 q=32  E1->E2
        int pb = 256 * (t >> 5), pk = t & 31;
#pragma unroll
        for (int j = 0; j < 8; j++) a[j] = sE1[PAD(pb + pk + 32 * j)];
        fwd8(a); twid_fwd(a, s_tw[16 * pk]);
#pragma unroll
        for (int r = 0; r < 8; r++) sE2[PAD(pb + 32 * r + pk)] = a[r];
    }
    __syncthreads();
    if (t < 256) {  // stage3: S=32 q=4  E2->E1
        int pb = 32 * (t >> 2), pk = t & 3;
#pragma unroll
        for (int j = 0; j < 8; j++) a[j] = sE2[PAD(pb + pk + 4 * j)];
        fwd8(a); twid_fwd(a, s_tw[128 * pk]);
#pragma unroll
        for (int r = 0; r < 8; r++) sE1[PAD(pb + 4 * r + pk)] = a[r];
    }
    __syncthreads();
    if (t < 256) {  // stage4: radix-4 x2, unscramble  E1->s_Z
#pragma unroll
        for (int h = 0; h < 2; h++) {
            int B = 2 * t + h;
            float2 b4[4];
#pragma unroll
            for (int j = 0; j < 4; j++) b4[j] = sE1[PAD(4 * B + j)];
            float2 e0 = cadd(b4[0], b4[2]), e1 = csub(b4[0], b4[2]);
            float2 o0 = cadd(b4[1], b4[3]), o1 = csub(b4[1], b4[3]);
            float2 y0 = cadd(e0, o0), y2 = csub(e0, o0);
            float2 y1 = make_float2(e1.x + o1.y, e1.y - o1.x);
            float2 y3 = make_float2(e1.x - o1.y, e1.y + o1.x);
            int f = (B >> 6) + 8 * ((B >> 3) & 7) + 64 * (B & 7);
            s_Z[PAD(f)] = y0; s_Z[PAD(f + 512)] = y1;
            s_Z[PAD(f + 1024)] = y2; s_Z[PAD(f + 1536)] = y3;
            if (B == 0) s_Z[2336] = y0;   // dup Z[0] at affine slot PAD(2048)
        }
    }
    __syncthreads();

    // ===== chirp rounds =====
    float2 c1r[4], Pr[4];
    const float sc = 1.0f / (4096.0f * (float)NF);
    const int lam = t & 7;
    const int S   = t >> 3;
    const float2 w64l = s_tw[64 * lam];
    const float2 wS0  = s_tw[S * lam];
    const float2 wS1  = s_tw[8 * S];
    const int B1 = PAD(64 * lam + S);
    const int B2 = 73 * S + lam;
    const int BM = PAD(512 - 64 * lam - S);
    const float2* Wp = g_W + 64 * S + 8 * lam;

#pragma unroll
    for (int s = 0; s < 4; s++) {
        bool useIr = (s == 0 || s == 2);
        const float4* UHp = (const float4*)(g_UH + s * 2048 + 4 * t);
        float4 uh01 = UHp[0], uh23 = UHp[1];

        // step1
#pragma unroll
        for (int r = 0; r < 4; r++) {
            float2 Zj = s_Z[B1 + 584 * r];
            float2 Zm = s_Z[BM + 584 * (3 - r)];
            float2 X = useIr
                ? make_float2(0.5f * (Zj.x + Zm.x), 0.5f * (Zj.y - Zm.y))
                : make_float2(0.5f * (Zj.y + Zm.y), 0.5f * (Zm.x - Zj.x));
            float2 uh = (r == 0) ? make_float2(uh01.x, uh01.y)
                      : (r == 1) ? make_float2(uh01.z, uh01.w)
                      : (r == 2) ? make_float2(uh23.x, uh23.y)
                                 : make_float2(uh23.z, uh23.w);
            a[r] = cmul(X, uh);
        }
        fwd8h(a); twid_fwd(a, w64l); transpose8(a, t); fwd8(a);
        twid_fwd_off(a, wS0, wS1);
#pragma unroll
        for (int r = 0; r < 8; r++) sE1[B1 + 584 * r] = a[r];
        __syncthreads();

        // middle
#pragma unroll
        for (int r = 0; r < 8; r++) a[r] = sE1[B2 + 9 * r];
        fwd64v(a, t, w64l);
        {
            const float4* W4 = (const float4*)Wp;
            float4 w = W4[0];
            a[0] = cmul(a[0], make_float2(w.x, w.y)); a[1] = cmul(a[1], make_float2(w.z, w.w));
            w = W4[1];
            a[2] = cmul(a[2], make_float2(w.x, w.y)); a[3] = cmul(a[3], make_float2(w.z, w.w));
            w = W4[2];
            a[4] = cmul(a[4], make_float2(w.x, w.y)); a[5] = cmul(a[5], make_float2(w.z, w.w));
            w = W4[3];
            a[6] = cmul(a[6], make_float2(w.x, w.y)); a[7] = cmul(a[7], make_float2(w.z, w.w));
        }
        inv64v(a, t, w64l);
        twid_inv_off(a, wS0, wS1);
#pragma unroll
        for (int r = 0; r < 8; r++) sE2[B1 + 584 * r] = a[r];
        __syncthreads();

        // step1'
#pragma unroll
        for (int r = 0; r < 8; r++) a[r] = sE2[B2 + 9 * r];
        inv64v_lo(a, t, w64l);
#pragma unroll
        for (int j = 0; j < 4; j++) {
            float2 v = make_float2(a[j].x * sc, a[j].y * sc);
            if (s == 0) c1r[j] = v;
            else if (s == 1) Pr[j] = cmul(c1r[j], v);
            else if (s == 2) c1r[j] = v;
            else {
                float2 p = cmul(c1r[j], v);
                Pr[j].x += p.x; Pr[j].y += p.y;
            }
        }
    }

    // ===== permute results to m = t + 512j layout (coalesced psi/out) =====
#pragma unroll
    for (int j = 0; j < 4; j++) sE1[B1 + 584 * j] = Pr[j];
    __syncthreads();
    {
        const int BT = PAD(t);
#pragma unroll
        for (int j = 0; j < 4; j++) {
            float2 p = sE1[BT + 584 * j];
            int m = t + 512 * j;
            float2 psi = g_psi[m];
            out[(b * T + m) * 9 + c] = p.x * psi.x - p.y * psi.y;
        }
    }
}

// ---------------- launch ----------------
extern "C" void kernel_launch(void* const* d_in, const int* in_sizes, int n_in,
                              void* d_out, int out_size) {
    const float* xd = (const float*)d_in[0];
    const float* A1 = (const float*)d_in[1];
    const float* A2 = (const float*)d_in[2];
    FnnW wf  = {(const float*)d_in[3],  (const float*)d_in[4],  (const float*)d_in[5],  (const float*)d_in[6]};
    FnnW wg  = {(const float*)d_in[7],  (const float*)d_in[8],  (const float*)d_in[9],  (const float*)d_in[10]};
    FnnW wfp = {(const float*)d_in[11], (const float*)d_in[12], (const float*)d_in[13], (const float*)d_in[14]};
    FnnW wgp = {(const float*)d_in[15], (const float*)d_in[16], (const float*)d_in[17], (const float*)d_in[18]};
    float* out = (float*)d_out;

    int smem_all = SMEM_ALL_F2 * sizeof(float2);   // 97,512 B
    cudaFuncSetAttribute(k_all, cudaFuncAttributeMaxDynamicSharedMemorySize, smem_all);

    k_all<<<NPRE + NMAIN, 512, smem_all>>>(out, xd, A1, A2, wf, wg, wfp, wgp);
}